// round 10
// baseline (speedup 1.0000x reference)
#include <cuda_runtime.h>
#include <cuda_bf16.h>

// SHEmbed: out[b,c] = clip( sum_j SH_j(ray_dir[b]) * sh_data[y[b], x[b], j, c], 0, 1 )
// L=3 -> 16 basis, 3 channels. H=W=1024, B=1048576.
// Inputs: y:int32[B], x:int32[B], ray_dir:f32[B,3], sh_data:f32[H,W,16,3]
// Output: f32[B,3]
//
// R9: revert R8's divergent L2-partition (regression: per-pair predicate split
// every warp, 2x LDG replay, zero traffic saved). Back to R6's uniform
// 2-lane LDG.256 gather, now with __launch_bounds__(256, 8): cap regs at 32 ->
// 2048 threads/SM (100% theoretical occupancy) to push HBM utilization from
// 75% toward its practical ceiling.

#define SH_W 1024
#define BLK  256

// 256-bit load with L2 evict_last (only legal evict form on sm_103a), 32B-aligned.
__device__ __forceinline__ void ldg256_keep(const float* __restrict__ p, float* v)
{
    unsigned r0, r1, r2, r3, r4, r5, r6, r7;
    asm("ld.global.nc.L2::evict_last.v8.b32 {%0,%1,%2,%3,%4,%5,%6,%7}, [%8];"
        : "=r"(r0), "=r"(r1), "=r"(r2), "=r"(r3),
          "=r"(r4), "=r"(r5), "=r"(r6), "=r"(r7)
        : "l"(p));
    v[0] = __uint_as_float(r0); v[1] = __uint_as_float(r1);
    v[2] = __uint_as_float(r2); v[3] = __uint_as_float(r3);
    v[4] = __uint_as_float(r4); v[5] = __uint_as_float(r5);
    v[6] = __uint_as_float(r6); v[7] = __uint_as_float(r7);
}

// Lane sub-id C (0/1) owns flat floats f = 16k + 8C + j (k=0..2, j=0..7);
// f -> (basis jj = f/3, channel = f%3), all compile-time.
template <int C>
__device__ __forceinline__ void dot_part(const float* __restrict__ b,
                                         const float* __restrict__ vv, // [24]
                                         float& a0, float& a1, float& a2)
{
    #pragma unroll
    for (int k = 0; k < 3; ++k) {
        #pragma unroll
        for (int j = 0; j < 8; ++j) {
            const int f  = 16 * k + 8 * C + j;
            const int jj = f / 3;
            const int ch = f % 3;
            float val = vv[8 * k + j];
            if      (ch == 0) a0 = fmaf(b[jj], val, a0);
            else if (ch == 1) a1 = fmaf(b[jj], val, a1);
            else              a2 = fmaf(b[jj], val, a2);
        }
    }
}

__global__ __launch_bounds__(BLK, 8)
void SHEmbed_69406671503663_kernel(const int* __restrict__ ys,
                                   const int* __restrict__ xs,
                                   const float* __restrict__ dir,
                                   const float* __restrict__ sh,
                                   float* __restrict__ out,
                                   int n)
{
    const int lane = threadIdx.x & 31;
    const int gw   = blockIdx.x * (BLK / 32) + (threadIdx.x >> 5);  // global warp id
    const int c    = lane & 1;                  // sub-id within lane pair
    const int r    = gw * 16 + (lane >> 1);     // ray owned by this pair
    const int rl   = r < n ? r : (n - 1);       // clamped for loads

    // ---- cell base (streaming index loads; pair -> broadcast) ----
    unsigned u = ((unsigned)__ldcs(ys + rl) * SH_W + (unsigned)__ldcs(xs + rl)) * 48u;
    const float* __restrict__ base = sh + u + c * 8;   // 32B-aligned

    // ---- direction first so its latency overlaps the gather ----
    float dx = __ldcs(dir + 3 * rl + 0);
    float dy = __ldcs(dir + 3 * rl + 1);
    float dz = __ldcs(dir + 3 * rl + 2);

    // ---- cooperative coef loads: 3 x LDG.256 per lane, pair covers 192B ----
    float vv[24];
    ldg256_keep(base +  0, vv +  0);
    ldg256_keep(base + 16, vv +  8);
    ldg256_keep(base + 32, vv + 16);

    // ---- closed-form L=3 real SH basis (reference signs) ----
    float inv = 1.0f / (sqrtf(fmaf(dx, dx, fmaf(dy, dy, dz * dz))) + 1e-14f);
    float x = dx * inv, y = dy * inv, z = dz * inv;
    float xx = x * x, yy = y * y, zz = z * z;

    float b[16];
    b[0]  =  0.28209479177387814f;
    b[1]  = -0.4886025119029199f * y;
    b[2]  =  0.4886025119029199f * z;
    b[3]  = -0.4886025119029199f * x;
    b[4]  =  1.0925484305920792f * x * y;
    b[5]  = -1.0925484305920792f * y * z;
    b[6]  =  0.31539156525252005f * (3.0f * zz - 1.0f);
    b[7]  = -1.0925484305920792f * x * z;
    b[8]  =  0.5462742152960396f * (xx - yy);
    b[9]  = -0.5900435899266435f * y * (3.0f * xx - yy);
    b[10] =  2.890611442640554f  * x * y * z;
    b[11] = -0.4570457994644658f * y * (5.0f * zz - 1.0f);
    b[12] =  0.3731763325901154f * z * (5.0f * zz - 3.0f);
    b[13] = -0.4570457994644658f * x * (5.0f * zz - 1.0f);
    b[14] =  1.445305721320277f  * z * (xx - yy);
    b[15] = -0.5900435899266435f * x * (xx - 3.0f * yy);

    // ---- partial dot, specialized on c ----
    float a0 = 0.f, a1 = 0.f, a2 = 0.f;
    if (c == 0) dot_part<0>(b, vv, a0, a1, a2);
    else        dot_part<1>(b, vv, a0, a1, a2);

    // ---- reduce across the lane pair ----
    a0 += __shfl_xor_sync(0xffffffffu, a0, 1);
    a1 += __shfl_xor_sync(0xffffffffu, a1, 1);
    a2 += __shfl_xor_sync(0xffffffffu, a2, 1);

    // ---- streaming store: even lane of each pair writes 3 floats ----
    if (r < n && c == 0) {
        __stcs(out + 3 * r + 0, fminf(fmaxf(a0, 0.0f), 1.0f));
        __stcs(out + 3 * r + 1, fminf(fmaxf(a1, 0.0f), 1.0f));
        __stcs(out + 3 * r + 2, fminf(fmaxf(a2, 0.0f), 1.0f));
    }
}

extern "C" void kernel_launch(void* const* d_in, const int* in_sizes, int n_in,
                              void* d_out, int out_size)
{
    const int*   ys  = (const int*)d_in[0];
    const int*   xs  = (const int*)d_in[1];
    const float* dir = (const float*)d_in[2];
    const float* sh  = (const float*)d_in[3];
    float*       out = (float*)d_out;

    int n = in_sizes[0];
    int warps  = (n + 15) / 16;                  // 16 rays per warp
    int blocks = (warps + (BLK / 32) - 1) / (BLK / 32);
    SHEmbed_69406671503663_kernel<<<blocks, BLK>>>(ys, xs, dir, sh, out, n);
}

// round 11
// speedup vs baseline: 1.2529x; 1.2529x over previous
#include <cuda_runtime.h>
#include <cuda_bf16.h>

// SHEmbed: out[b,c] = clip( sum_j SH_j(ray_dir[b]) * sh_data[y[b], x[b], j, c], 0, 1 )
// L=3 -> 16 basis, 3 channels. H=W=1024, B=1048576.
// Inputs: y:int32[B], x:int32[B], ray_dir:f32[B,3], sh_data:f32[H,W,16,3]
// Output: f32[B,3]
//
// R10: R6's 2-lane LDG.256 cooperative gather (33.2us, best) + software
// pipelining: each lane-pair processes 4 rays (r = g + t*P, warp-coalesced at
// every t), prefetching ray t+1's index+dir while ray t's coef loads drain.
// No reg cap (R9's 32-reg squeeze spilled and regressed); vv[] recycles per
// iteration so regs stay ~46.

#define SH_W 1024
#define BLK  256
#define TPER 4   // rays per lane-pair

// 256-bit load with L2 evict_last (only legal evict form), 32B-aligned.
__device__ __forceinline__ void ldg256_keep(const float* __restrict__ p, float* v)
{
    unsigned r0, r1, r2, r3, r4, r5, r6, r7;
    asm("ld.global.nc.L2::evict_last.v8.b32 {%0,%1,%2,%3,%4,%5,%6,%7}, [%8];"
        : "=r"(r0), "=r"(r1), "=r"(r2), "=r"(r3),
          "=r"(r4), "=r"(r5), "=r"(r6), "=r"(r7)
        : "l"(p));
    v[0] = __uint_as_float(r0); v[1] = __uint_as_float(r1);
    v[2] = __uint_as_float(r2); v[3] = __uint_as_float(r3);
    v[4] = __uint_as_float(r4); v[5] = __uint_as_float(r5);
    v[6] = __uint_as_float(r6); v[7] = __uint_as_float(r7);
}

// Lane sub-id C (0/1) owns flat floats f = 16k + 8C + j (k=0..2, j=0..7);
// f -> (basis jj = f/3, channel = f%3), all compile-time.
template <int C>
__device__ __forceinline__ void dot_part(const float* __restrict__ b,
                                         const float* __restrict__ vv, // [24]
                                         float& a0, float& a1, float& a2)
{
    #pragma unroll
    for (int k = 0; k < 3; ++k) {
        #pragma unroll
        for (int j = 0; j < 8; ++j) {
            const int f  = 16 * k + 8 * C + j;
            const int jj = f / 3;
            const int ch = f % 3;
            float val = vv[8 * k + j];
            if      (ch == 0) a0 = fmaf(b[jj], val, a0);
            else if (ch == 1) a1 = fmaf(b[jj], val, a1);
            else              a2 = fmaf(b[jj], val, a2);
        }
    }
}

__global__ __launch_bounds__(BLK)
void SHEmbed_69406671503663_kernel(const int* __restrict__ ys,
                                   const int* __restrict__ xs,
                                   const float* __restrict__ dir,
                                   const float* __restrict__ sh,
                                   float* __restrict__ out,
                                   int n)
{
    const int c = threadIdx.x & 1;                              // sub-id in pair
    const int g = blockIdx.x * (BLK / 2) + (threadIdx.x >> 1);  // global pair id
    const int P = (n + TPER - 1) / TPER;                        // pairs total

    // ---- prologue: prefetch ray t=0's index + direction ----
    int r0i = g;
    int rl  = r0i < n ? r0i : (n - 1);
    unsigned u_next = ((unsigned)__ldcs(ys + rl) * SH_W + (unsigned)__ldcs(xs + rl)) * 48u;
    float dxn = __ldcs(dir + 3 * rl + 0);
    float dyn = __ldcs(dir + 3 * rl + 1);
    float dzn = __ldcs(dir + 3 * rl + 2);

    #pragma unroll
    for (int t = 0; t < TPER; ++t) {
        const int r = g + t * P;          // this iteration's ray (warp-coalesced)
        unsigned u = u_next;
        float dx = dxn, dy = dyn, dz = dzn;

        // ---- issue this ray's coef loads immediately ----
        const float* __restrict__ base = sh + u + c * 8;   // 32B-aligned
        float vv[24];
        ldg256_keep(base +  0, vv +  0);
        ldg256_keep(base + 16, vv +  8);
        ldg256_keep(base + 32, vv + 16);

        // ---- prefetch next ray's index + direction (overlaps coef latency) ----
        if (t + 1 < TPER) {
            int r2  = g + (t + 1) * P;
            int rl2 = r2 < n ? r2 : (n - 1);
            u_next = ((unsigned)__ldcs(ys + rl2) * SH_W + (unsigned)__ldcs(xs + rl2)) * 48u;
            dxn = __ldcs(dir + 3 * rl2 + 0);
            dyn = __ldcs(dir + 3 * rl2 + 1);
            dzn = __ldcs(dir + 3 * rl2 + 2);
        }

        // ---- closed-form L=3 real SH basis (reference signs) ----
        float inv = 1.0f / (sqrtf(fmaf(dx, dx, fmaf(dy, dy, dz * dz))) + 1e-14f);
        float x = dx * inv, y = dy * inv, z = dz * inv;
        float xx = x * x, yy = y * y, zz = z * z;

        float b[16];
        b[0]  =  0.28209479177387814f;
        b[1]  = -0.4886025119029199f * y;
        b[2]  =  0.4886025119029199f * z;
        b[3]  = -0.4886025119029199f * x;
        b[4]  =  1.0925484305920792f * x * y;
        b[5]  = -1.0925484305920792f * y * z;
        b[6]  =  0.31539156525252005f * (3.0f * zz - 1.0f);
        b[7]  = -1.0925484305920792f * x * z;
        b[8]  =  0.5462742152960396f * (xx - yy);
        b[9]  = -0.5900435899266435f * y * (3.0f * xx - yy);
        b[10] =  2.890611442640554f  * x * y * z;
        b[11] = -0.4570457994644658f * y * (5.0f * zz - 1.0f);
        b[12] =  0.3731763325901154f * z * (5.0f * zz - 3.0f);
        b[13] = -0.4570457994644658f * x * (5.0f * zz - 1.0f);
        b[14] =  1.445305721320277f  * z * (xx - yy);
        b[15] = -0.5900435899266435f * x * (xx - 3.0f * yy);

        // ---- partial dot, specialized on c ----
        float a0 = 0.f, a1 = 0.f, a2 = 0.f;
        if (c == 0) dot_part<0>(b, vv, a0, a1, a2);
        else        dot_part<1>(b, vv, a0, a1, a2);

        // ---- reduce across the lane pair ----
        a0 += __shfl_xor_sync(0xffffffffu, a0, 1);
        a1 += __shfl_xor_sync(0xffffffffu, a1, 1);
        a2 += __shfl_xor_sync(0xffffffffu, a2, 1);

        // ---- streaming store: even lane writes 3 floats (warp-coalesced) ----
        if (r < n && c == 0) {
            __stcs(out + 3 * r + 0, fminf(fmaxf(a0, 0.0f), 1.0f));
            __stcs(out + 3 * r + 1, fminf(fmaxf(a1, 0.0f), 1.0f));
            __stcs(out + 3 * r + 2, fminf(fmaxf(a2, 0.0f), 1.0f));
        }
    }
}

extern "C" void kernel_launch(void* const* d_in, const int* in_sizes, int n_in,
                              void* d_out, int out_size)
{
    const int*   ys  = (const int*)d_in[0];
    const int*   xs  = (const int*)d_in[1];
    const float* dir = (const float*)d_in[2];
    const float* sh  = (const float*)d_in[3];
    float*       out = (float*)d_out;

    int n = in_sizes[0];
    int pairs  = (n + TPER - 1) / TPER;          // lane-pairs needed
    int blocks = (pairs + (BLK / 2) - 1) / (BLK / 2);
    SHEmbed_69406671503663_kernel<<<blocks, BLK>>>(ys, xs, dir, sh, out, n);
}